// round 14
// baseline (speedup 1.0000x reference)
#include <cuda_runtime.h>
#include <cuda_bf16.h>
#include <cstdint>

// Problem constants (from reference)
#define B_  8
#define L_  2048
#define P_  576
#define V_  32000
#define D_  2560
#define T_  (L_ - 1 + P_)      // 2623
#define N_ROWS_ (B_ * T_)      // 20984
#define IGNORE_INDEX_ (-100)

// Write-through float4 store: output stream takes no L2 lines.
__device__ __forceinline__ void stwt4(float4* p, float4 v) {
    asm volatile("st.global.wt.v4.f32 [%0], {%1,%2,%3,%4};"
                 :: "l"(p), "f"(v.x), "f"(v.y), "f"(v.z), "f"(v.w)
                 : "memory");
}

// Two rows per block, flat (no loop-carried dependence): both rows' 5 loads
// are materialized into registers before any store, giving 10 front-batched
// loads per thread and halving the grid (fewer waves / prologues).
//
// Cache policy unchanged from champion:
//   embed_table    -> __ldg  (reused, L2-cached)
//   image_features -> __ldcs (read-once streaming)
//   output         -> st.wt  (no L2 footprint)
__global__ void __launch_bounds__(128)
splice_kernel2(const float* __restrict__ embed_table,     // [V, D]
               const float* __restrict__ image_features,  // [B, P, D]
               const int*   __restrict__ input_ids,       // [B, L]
               const int*   __restrict__ labels,          // [B, L]
               const int*   __restrict__ img_pos,         // [B]
               float* __restrict__ out)
{
    const int tid = threadIdx.x;
    const int row0 = blockIdx.x * 2;
    const int row1 = row0 + 1;              // N_ROWS_ is even (20984)

    // ---- row 0 index math ----
    const int b0 = row0 / T_;
    const int t0 = row0 - b0 * T_;
    const int pos0 = img_pos[b0];
    const bool im0 = (t0 >= pos0) && (t0 < pos0 + P_);
    int ti0 = (t0 < pos0) ? t0 : (t0 - P_ + 1);
    ti0 = max(0, min(ti0, L_ - 1));

    // ---- row 1 index math ----
    const int b1 = row1 / T_;
    const int t1 = row1 - b1 * T_;
    const int pos1 = img_pos[b1];
    const bool im1 = (t1 >= pos1) && (t1 < pos1 + P_);
    int ti1 = (t1 < pos1) ? t1 : (t1 - P_ + 1);
    ti1 = max(0, min(ti1, L_ - 1));

    // ---- front-batched loads: row 0 then row 1, no stores in between ----
    float4 a0, a1, a2, a3, a4;   // row 0 payload
    float4 c0, c1, c2, c3, c4;   // row 1 payload

    if (im0) {
        const int ii = max(0, min(t0 - pos0, P_ - 1));
        const float4* __restrict__ src = reinterpret_cast<const float4*>(
            image_features + ((long long)b0 * P_ + ii) * D_);
        a0 = __ldcs(src + tid);
        a1 = __ldcs(src + tid + 128);
        a2 = __ldcs(src + tid + 256);
        a3 = __ldcs(src + tid + 384);
        a4 = __ldcs(src + tid + 512);
    } else {
        const int tok = input_ids[b0 * L_ + ti0];
        const float4* __restrict__ src = reinterpret_cast<const float4*>(
            embed_table + (long long)tok * D_);
        a0 = __ldg(src + tid);
        a1 = __ldg(src + tid + 128);
        a2 = __ldg(src + tid + 256);
        a3 = __ldg(src + tid + 384);
        a4 = __ldg(src + tid + 512);
    }

    if (im1) {
        const int ii = max(0, min(t1 - pos1, P_ - 1));
        const float4* __restrict__ src = reinterpret_cast<const float4*>(
            image_features + ((long long)b1 * P_ + ii) * D_);
        c0 = __ldcs(src + tid);
        c1 = __ldcs(src + tid + 128);
        c2 = __ldcs(src + tid + 256);
        c3 = __ldcs(src + tid + 384);
        c4 = __ldcs(src + tid + 512);
    } else {
        const int tok = input_ids[b1 * L_ + ti1];
        const float4* __restrict__ src = reinterpret_cast<const float4*>(
            embed_table + (long long)tok * D_);
        c0 = __ldg(src + tid);
        c1 = __ldg(src + tid + 128);
        c2 = __ldg(src + tid + 256);
        c3 = __ldg(src + tid + 384);
        c4 = __ldg(src + tid + 512);
    }

    // ---- stores ----
    float4* __restrict__ d0 =
        reinterpret_cast<float4*>(out + (long long)row0 * D_);
    float4* __restrict__ d1 =
        reinterpret_cast<float4*>(out + (long long)row1 * D_);

    stwt4(d0 + tid,       a0);
    stwt4(d0 + tid + 128, a1);
    stwt4(d0 + tid + 256, a2);
    stwt4(d0 + tid + 384, a3);
    stwt4(d0 + tid + 512, a4);
    stwt4(d1 + tid,       c0);
    stwt4(d1 + tid + 128, c1);
    stwt4(d1 + tid + 256, c2);
    stwt4(d1 + tid + 384, c3);
    stwt4(d1 + tid + 512, c4);

    // ---- scalar tails (both rows), proven free under DRAM latency ----
    if (tid == 0) {
        float* tails = out + (long long)N_ROWS_ * D_;
        tails[row0] = im0 ? (float)IGNORE_INDEX_
                          : (float)labels[b0 * L_ + ti0];
        tails[row1] = im1 ? (float)IGNORE_INDEX_
                          : (float)labels[b1 * L_ + ti1];
        tails[(long long)N_ROWS_ + row0] = 1.0f;
        tails[(long long)N_ROWS_ + row1] = 1.0f;
        tails[2LL * N_ROWS_ + row0] = (float)t0;
        tails[2LL * N_ROWS_ + row1] = (float)t1;
    }
}

extern "C" void kernel_launch(void* const* d_in, const int* in_sizes, int n_in,
                              void* d_out, int out_size)
{
    const float* embed_table    = (const float*)d_in[0];
    const float* image_features = (const float*)d_in[1];
    const int*   input_ids      = (const int*)  d_in[2];
    const int*   labels         = (const int*)  d_in[3];
    const int*   img_pos        = (const int*)  d_in[4];
    float* out = (float*)d_out;

    splice_kernel2<<<N_ROWS_ / 2, 128>>>(embed_table, image_features,
                                         input_ids, labels, img_pos, out);
}

// round 15
// speedup vs baseline: 1.0014x; 1.0014x over previous
#include <cuda_runtime.h>
#include <cuda_bf16.h>
#include <cstdint>

// Problem constants (from reference)
#define B_  8
#define L_  2048
#define P_  576
#define V_  32000
#define D_  2560
#define T_  (L_ - 1 + P_)      // 2623
#define IGNORE_INDEX_ (-100)

// Write-through float4 store: output stream takes no L2 lines.
__device__ __forceinline__ void stwt4(float4* p, float4 v) {
    asm volatile("st.global.wt.v4.f32 [%0], {%1,%2,%3,%4};"
                 :: "l"(p), "f"(v.x), "f"(v.y), "f"(v.z), "f"(v.w)
                 : "memory");
}

// FINAL champion (best of 14 measured variants: dur 66.0us, kernel 59.4us,
// 6.0TB/s ~= 96% of the mixed read/write HBM ceiling).
//
// One block per output row (b, t). 128 threads, 640 float4 per row ->
// exactly 5 unconditional float4 per thread, loads front-batched (MLP=5;
// measured saturation point — 2.5 was under, 10 gains nothing).
//
// Cache policy (the load-bearing choices, each A/B-measured):
//   embed_table    -> __ldg  : reused working set (~128MB), L2-cached;
//                              repeated rows dedup'd by L2 (-40MB DRAM)
//   image_features -> __ldcs : read-once streaming, evict-first
//   output         -> st.wt  : write-through, zero L2 allocation — keeps
//                              the 215MB output stream from evicting the
//                              embed working set
//
// Scalar tails via tid0: measured free (hidden under DRAM latency; all
// coalesced/split/fused alternatives measured tie or worse).
__global__ void __launch_bounds__(128)
splice_kernel(const float* __restrict__ embed_table,     // [V, D]
              const float* __restrict__ image_features,  // [B, P, D]
              const int*   __restrict__ input_ids,       // [B, L]
              const int*   __restrict__ labels,          // [B, L]
              const int*   __restrict__ img_pos,         // [B]
              float* __restrict__ out)
{
    const int row = blockIdx.x;           // 0 .. B*T-1
    const int b = row / T_;
    const int t = row - b * T_;

    const int pos = img_pos[b];
    const bool is_img = (t >= pos) && (t < pos + P_);

    int tok_idx = (t < pos) ? t : (t - P_ + 1);
    tok_idx = max(0, min(tok_idx, L_ - 1));

    float4* __restrict__ dst =
        reinterpret_cast<float4*>(out + (long long)row * D_);

    const int tid = threadIdx.x;

    if (is_img) {
        const int img_idx = max(0, min(t - pos, P_ - 1));
        const float4* __restrict__ src = reinterpret_cast<const float4*>(
            image_features + ((long long)b * P_ + img_idx) * D_);
        float4 v0 = __ldcs(src + tid);
        float4 v1 = __ldcs(src + tid + 128);
        float4 v2 = __ldcs(src + tid + 256);
        float4 v3 = __ldcs(src + tid + 384);
        float4 v4 = __ldcs(src + tid + 512);
        stwt4(dst + tid,       v0);
        stwt4(dst + tid + 128, v1);
        stwt4(dst + tid + 256, v2);
        stwt4(dst + tid + 384, v3);
        stwt4(dst + tid + 512, v4);
    } else {
        const int tok = input_ids[b * L_ + tok_idx];
        const float4* __restrict__ src = reinterpret_cast<const float4*>(
            embed_table + (long long)tok * D_);
        float4 v0 = __ldg(src + tid);
        float4 v1 = __ldg(src + tid + 128);
        float4 v2 = __ldg(src + tid + 256);
        float4 v3 = __ldg(src + tid + 384);
        float4 v4 = __ldg(src + tid + 512);
        stwt4(dst + tid,       v0);
        stwt4(dst + tid + 128, v1);
        stwt4(dst + tid + 256, v2);
        stwt4(dst + tid + 384, v3);
        stwt4(dst + tid + 512, v4);
    }

    if (tid == 0) {
        float* tails = out + (long long)B_ * T_ * D_;
        // new_labels
        tails[row] = is_img ? (float)IGNORE_INDEX_
                            : (float)labels[b * L_ + tok_idx];
        // attention_mask (all true)
        tails[(long long)B_ * T_ + row] = 1.0f;
        // position_ids (iota over T)
        tails[2LL * B_ * T_ + row] = (float)t;
    }
}

extern "C" void kernel_launch(void* const* d_in, const int* in_sizes, int n_in,
                              void* d_out, int out_size)
{
    const float* embed_table    = (const float*)d_in[0];
    const float* image_features = (const float*)d_in[1];
    const int*   input_ids      = (const int*)  d_in[2];
    const int*   labels         = (const int*)  d_in[3];
    const int*   img_pos        = (const int*)  d_in[4];
    float* out = (float*)d_out;

    const int n_rows = B_ * T_;   // 20984
    splice_kernel<<<n_rows, 128>>>(embed_table, image_features,
                                   input_ids, labels, img_pos, out);
}

// round 16
// speedup vs baseline: 1.0116x; 1.0102x over previous
#include <cuda_runtime.h>
#include <cuda_bf16.h>
#include <cstdint>

// Problem constants (from reference)
#define B_  8
#define L_  2048
#define P_  576
#define V_  32000
#define D_  2560
#define T_  (L_ - 1 + P_)      // 2623
#define IGNORE_INDEX_ (-100)

// Write-through float4 store: output stream takes no L2 lines.
__device__ __forceinline__ void stwt4(float4* p, float4 v) {
    asm volatile("st.global.wt.v4.f32 [%0], {%1,%2,%3,%4};"
                 :: "l"(p), "f"(v.x), "f"(v.y), "f"(v.z), "f"(v.w)
                 : "memory");
}

// FINAL champion — 15-round convergence at the mixed R/W HBM ceiling.
// dur 66.0us (noise band 66.0-66.7), kernel ~59.5us @ 6.0TB/s over ~359MB
// compulsory traffic (~96% of achievable mixed-stream bandwidth).
//
// One block per output row (b, t). 128 threads, 640 float4 per row ->
// exactly 5 unconditional float4 per thread, loads front-batched (MLP=5,
// measured saturation point; occupancy 46-88% measured bandwidth-invariant).
//
// Cache policy (each choice A/B-measured):
//   embed_table    -> __ldg  : reused ~128MB working set, L2-cached; L2
//                              dedups repeated rows and retains lines
//                              across graph replays
//   image_features -> __ldcs : read-once streaming, evict-first
//   output         -> st.wt  : write-through, zero L2 allocation — keeps
//                              the 215MB output stream from evicting the
//                              embed working set
//
// Scalar tails via tid0: measured free (hidden under DRAM latency; split
// kernels, grid-appended and wave-0 coalesced variants all tie or regress).
__global__ void __launch_bounds__(128)
splice_kernel(const float* __restrict__ embed_table,     // [V, D]
              const float* __restrict__ image_features,  // [B, P, D]
              const int*   __restrict__ input_ids,       // [B, L]
              const int*   __restrict__ labels,          // [B, L]
              const int*   __restrict__ img_pos,         // [B]
              float* __restrict__ out)
{
    const int row = blockIdx.x;           // 0 .. B*T-1
    const int b = row / T_;
    const int t = row - b * T_;

    const int pos = img_pos[b];
    const bool is_img = (t >= pos) && (t < pos + P_);

    int tok_idx = (t < pos) ? t : (t - P_ + 1);
    tok_idx = max(0, min(tok_idx, L_ - 1));

    float4* __restrict__ dst =
        reinterpret_cast<float4*>(out + (long long)row * D_);

    const int tid = threadIdx.x;

    if (is_img) {
        const int img_idx = max(0, min(t - pos, P_ - 1));
        const float4* __restrict__ src = reinterpret_cast<const float4*>(
            image_features + ((long long)b * P_ + img_idx) * D_);
        float4 v0 = __ldcs(src + tid);
        float4 v1 = __ldcs(src + tid + 128);
        float4 v2 = __ldcs(src + tid + 256);
        float4 v3 = __ldcs(src + tid + 384);
        float4 v4 = __ldcs(src + tid + 512);
        stwt4(dst + tid,       v0);
        stwt4(dst + tid + 128, v1);
        stwt4(dst + tid + 256, v2);
        stwt4(dst + tid + 384, v3);
        stwt4(dst + tid + 512, v4);
    } else {
        const int tok = input_ids[b * L_ + tok_idx];
        const float4* __restrict__ src = reinterpret_cast<const float4*>(
            embed_table + (long long)tok * D_);
        float4 v0 = __ldg(src + tid);
        float4 v1 = __ldg(src + tid + 128);
        float4 v2 = __ldg(src + tid + 256);
        float4 v3 = __ldg(src + tid + 384);
        float4 v4 = __ldg(src + tid + 512);
        stwt4(dst + tid,       v0);
        stwt4(dst + tid + 128, v1);
        stwt4(dst + tid + 256, v2);
        stwt4(dst + tid + 384, v3);
        stwt4(dst + tid + 512, v4);
    }

    if (tid == 0) {
        float* tails = out + (long long)B_ * T_ * D_;
        // new_labels
        tails[row] = is_img ? (float)IGNORE_INDEX_
                            : (float)labels[b * L_ + tok_idx];
        // attention_mask (all true)
        tails[(long long)B_ * T_ + row] = 1.0f;
        // position_ids (iota over T)
        tails[2LL * B_ * T_ + row] = (float)t;
    }
}

extern "C" void kernel_launch(void* const* d_in, const int* in_sizes, int n_in,
                              void* d_out, int out_size)
{
    const float* embed_table    = (const float*)d_in[0];
    const float* image_features = (const float*)d_in[1];
    const int*   input_ids      = (const int*)  d_in[2];
    const int*   labels         = (const int*)  d_in[3];
    const int*   img_pos        = (const int*)  d_in[4];
    float* out = (float*)d_out;

    const int n_rows = B_ * T_;   // 20984
    splice_kernel<<<n_rows, 128>>>(embed_table, image_features,
                                   input_ids, labels, img_pos, out);
}